// round 4
// baseline (speedup 1.0000x reference)
#include <cuda_runtime.h>
#include <cstdint>
#include <cstddef>

// ---------------------------------------------------------------------------
// Fixed shapes: N=100000, E=1600000, F 128 -> 128 -> 64
// ---------------------------------------------------------------------------
#define MAX_N 100000

// Scratch (device BSS — no allocation inside kernel_launch)
__device__ float g_buf [(size_t)MAX_N * 128];  // x @ W1
__device__ float h1_buf[(size_t)MAX_N * 128];  // spmm(A, g)
__device__ float h_buf [(size_t)MAX_N * 128];  // relu+bias+dropout(h1)
__device__ float p_buf [(size_t)MAX_N * 64];   // h @ W2

// ---------------------------------------------------------------------------
// Threefry-2x32, key = (0, 42) — bit-exact replica of jax threefry2x32 core
// ---------------------------------------------------------------------------
__device__ __forceinline__ void threefry_0_42(uint32_t x0, uint32_t x1,
                                              uint32_t& o0, uint32_t& o1)
{
    const uint32_t k0 = 0u, k1 = 42u;
    const uint32_t k2 = k0 ^ k1 ^ 0x1BD11BDAu;
    x0 += k0; x1 += k1;
#define TF_R(r) { x0 += x1; x1 = (x1 << (r)) | (x1 >> (32 - (r))); x1 ^= x0; }
    TF_R(13) TF_R(15) TF_R(26) TF_R(6)   x0 += k1; x1 += k2 + 1u;
    TF_R(17) TF_R(29) TF_R(16) TF_R(24)  x0 += k2; x1 += k0 + 2u;
    TF_R(13) TF_R(15) TF_R(26) TF_R(6)   x0 += k0; x1 += k1 + 3u;
    TF_R(17) TF_R(29) TF_R(16) TF_R(24)  x0 += k1; x1 += k2 + 4u;
    TF_R(13) TF_R(15) TF_R(26) TF_R(6)   x0 += k2; x1 += k0 + 5u;
#undef TF_R
    o0 = x0; o1 = x1;
}

// ---------------------------------------------------------------------------
// Packed fp32x2 FMA helpers (Blackwell FFMA2 — only reachable via PTX)
// ---------------------------------------------------------------------------
#define FMA2(acc_, a_, b_) \
    asm("fma.rn.f32x2 %0, %1, %2, %0;" : "+l"(acc_) : "l"(a_), "l"(b_))

__device__ __forceinline__ unsigned long long dup2(float a)
{
    unsigned long long r;
    asm("mov.b64 %0, {%1, %1};" : "=l"(r) : "r"(__float_as_uint(a)));
    return r;
}

// ---------------------------------------------------------------------------
// init: h1 = 0 ; out = broadcast(b2)
// ---------------------------------------------------------------------------
__global__ void init_kernel(float* __restrict__ out,
                            const float* __restrict__ b2, int N)
{
    const int i = blockIdx.x * blockDim.x + threadIdx.x;
    if (i < N * 128) h1_buf[i] = 0.0f;
    if (i < N * 64)  out[i] = b2[i & 63];
}

// ---------------------------------------------------------------------------
// GEMM:  C[M, BN] = A[M, 128] @ B[128, BN]   (BN = 128 or 64, K = 128 fixed)
// 256 threads, 128-row tile, 8x(4|8) microtile in packed f32x2 accumulators.
// (certified vs naive reference path in R2/R3: identical outputs)
// ---------------------------------------------------------------------------
template<int BN, bool A_IS_H>
__global__ void __launch_bounds__(256, 2)
gemm_k128(const float* __restrict__ Aarg, const float* __restrict__ B, int M)
{
    const float* __restrict__ A = A_IS_H ? h_buf : Aarg;
    float* __restrict__ C       = A_IS_H ? p_buf : g_buf;

    __shared__ __align__(16) float As[2][16 * 128];  // [k][m], transposed
    __shared__ __align__(16) float Bs[2][16 * BN];   // [k][n]

    const int tid = threadIdx.x;
    const int tx  = tid & 15;
    const int ty  = tid >> 4;
    const int m0  = blockIdx.x * 128;
    const int lr  = tid >> 2;
    const int lc  = tid & 3;

    constexpr int NG = BN / 64;
    unsigned long long acc[8][2 * NG];
#pragma unroll
    for (int r = 0; r < 8; r++)
#pragma unroll
        for (int j = 0; j < 2 * NG; j++) acc[r][j] = 0ull;

    auto loadTiles = [&](int buf, int kk) {
#pragma unroll
        for (int rr = 0; rr < 2; rr++) {
            int row = m0 + lr + rr * 64;
            if (row > M - 1) row = M - 1;
            const float4 v = *(const float4*)(A + (size_t)row * 128 + kk + lc * 4);
            float* d = &As[buf][0];
            const int mi = lr + rr * 64;
            d[(lc * 4 + 0) * 128 + mi] = v.x;
            d[(lc * 4 + 1) * 128 + mi] = v.y;
            d[(lc * 4 + 2) * 128 + mi] = v.z;
            d[(lc * 4 + 3) * 128 + mi] = v.w;
        }
#pragma unroll
        for (int i = 0; i < (16 * BN) / 1024; i++) {
            const int idx = (i * 256 + tid) * 4;
            *(float4*)&Bs[buf][idx] = *(const float4*)(B + kk * BN + idx);
        }
    };

    loadTiles(0, 0);
    __syncthreads();

#pragma unroll 1
    for (int kk = 0; kk < 128; kk += 16) {
        const int cur = (kk >> 4) & 1;
        if (kk + 16 < 128) loadTiles(cur ^ 1, kk + 16);
#pragma unroll
        for (int k = 0; k < 16; k++) {
            const float4 a0 = *(const float4*)&As[cur][k * 128 + ty * 4];
            const float4 a1 = *(const float4*)&As[cur][k * 128 + ty * 4 + 64];
            unsigned long long a2[8];
            a2[0] = dup2(a0.x); a2[1] = dup2(a0.y);
            a2[2] = dup2(a0.z); a2[3] = dup2(a0.w);
            a2[4] = dup2(a1.x); a2[5] = dup2(a1.y);
            a2[6] = dup2(a1.z); a2[7] = dup2(a1.w);
#pragma unroll
            for (int g = 0; g < NG; g++) {
                const double2 b = *(const double2*)&Bs[cur][k * BN + tx * 4 + g * 64];
                const unsigned long long bl = __double_as_longlong(b.x);
                const unsigned long long bh = __double_as_longlong(b.y);
#pragma unroll
                for (int r = 0; r < 8; r++) {
                    FMA2(acc[r][2 * g + 0], a2[r], bl);
                    FMA2(acc[r][2 * g + 1], a2[r], bh);
                }
            }
        }
        __syncthreads();
    }

#pragma unroll
    for (int r = 0; r < 8; r++) {
        const int row = m0 + ty * 4 + (r >> 2) * 64 + (r & 3);
        if (row < M) {
#pragma unroll
            for (int g = 0; g < NG; g++) {
                const unsigned long long v0 = acc[r][2 * g + 0];
                const unsigned long long v1 = acc[r][2 * g + 1];
                float4 o;
                o.x = __uint_as_float((unsigned)(v0 & 0xffffffffu));
                o.y = __uint_as_float((unsigned)(v0 >> 32));
                o.z = __uint_as_float((unsigned)(v1 & 0xffffffffu));
                o.w = __uint_as_float((unsigned)(v1 >> 32));
                *(float4*)(C + (size_t)row * BN + tx * 4 + g * 64) = o;
            }
        }
    }
}

// ---------------------------------------------------------------------------
// SpMM, F=128: one warp per edge.  h1[dst] += w * g[src]
// ---------------------------------------------------------------------------
__global__ void spmm_f128(const int* __restrict__ src, const int* __restrict__ dst,
                          const float* __restrict__ ew, int E)
{
    const int e    = (blockIdx.x * blockDim.x + threadIdx.x) >> 5;
    const int lane = threadIdx.x & 31;
    if (e >= E) return;
    const int   s = __ldg(&src[e]);
    const int   d = __ldg(&dst[e]);
    const float w = __ldg(&ew[e]);

    const float4 v = *(const float4*)(g_buf + (size_t)s * 128 + lane * 4);
    float* addr = h1_buf + (size_t)d * 128 + lane * 4;
    asm volatile("red.global.add.v4.f32 [%0], {%1, %2, %3, %4};"
                 :: "l"(addr), "f"(v.x * w), "f"(v.y * w), "f"(v.z * w), "f"(v.w * w)
                 : "memory");
}

// ---------------------------------------------------------------------------
// SpMM, F=64: one half-warp per edge.  out[dst] += w * p[src]
// ---------------------------------------------------------------------------
__global__ void spmm_f64(const int* __restrict__ src, const int* __restrict__ dst,
                         const float* __restrict__ ew, float* __restrict__ out, int E)
{
    const int e    = (blockIdx.x * blockDim.x + threadIdx.x) >> 4;
    const int lane = threadIdx.x & 15;
    if (e >= E) return;
    const int   s = __ldg(&src[e]);
    const int   d = __ldg(&dst[e]);
    const float w = __ldg(&ew[e]);

    const float4 v = *(const float4*)(p_buf + (size_t)s * 64 + lane * 4);
    float* addr = out + (size_t)d * 64 + lane * 4;
    asm volatile("red.global.add.v4.f32 [%0], {%1, %2, %3, %4};"
                 :: "l"(addr), "f"(v.x * w), "f"(v.y * w), "f"(v.z * w), "f"(v.w * w)
                 : "memory");
}

// ---------------------------------------------------------------------------
// Elementwise: h = relu(h1 + b1) * dropout_mask * 2
//
// Mask = JAX partitionable threefry (default in modern jax):
//   per-element u64 counter i -> (o0, o1) = threefry2x32(key, (i>>32, i&0xffffffff))
//   for bit_width < 64:  bits = o0 ^ o1   (XOR-fold of the two output words)
//   keep  <=>  uniform(bits) < 0.5  <=>  top bit of bits == 0.
// Size 12.8M < 2^32 so the hi counter word is always 0.
// ---------------------------------------------------------------------------
__global__ void relu_bias_dropout(const float* __restrict__ b1, int TOT)
{
    const int i = blockIdx.x * blockDim.x + threadIdx.x;
    if (i >= TOT) return;

    uint32_t o0, o1;
    threefry_0_42(0u, (uint32_t)i, o0, o1);
    const uint32_t bits = o0 ^ o1;   // XOR-fold (partitionable, bit_width=32)

    const float bias = __ldg(&b1[i & 127]);
    float v = h1_buf[i] + bias;
    v = fmaxf(v, 0.0f);
    h_buf[i] = (bits & 0x80000000u) ? 0.0f : v * 2.0f;
}

// ---------------------------------------------------------------------------
// kernel_launch
// inputs: x, edge_weight, W1, b1, W2, b2, src, dst, n_nodes
// ---------------------------------------------------------------------------
extern "C" void kernel_launch(void* const* d_in, const int* in_sizes, int n_in,
                              void* d_out, int out_size)
{
    const float* x   = (const float*)d_in[0];
    const float* ew  = (const float*)d_in[1];
    const float* W1  = (const float*)d_in[2];
    const float* b1  = (const float*)d_in[3];
    const float* W2  = (const float*)d_in[4];
    const float* b2  = (const float*)d_in[5];
    const int*   src = (const int*)d_in[6];
    const int*   dst = (const int*)d_in[7];

    const int N = in_sizes[0] / 128;
    const int E = in_sizes[1];
    float* out = (float*)d_out;

    // 1) h1 = 0 ; out = b2 (spmm2 accumulates on top of bias)
    init_kernel<<<(N * 128 + 255) / 256, 256>>>(out, b2, N);
    // 2) g = x @ W1      (reordered: spmm(A,x)@W1 == spmm(A, x@W1))
    gemm_k128<128, false><<<(N + 127) / 128, 256>>>(x, W1, N);
    // 3) h1[dst] += w * g[src]
    spmm_f128<<<(E + 7) / 8, 256>>>(src, dst, ew, E);
    // 4) h = relu(h1 + b1) * mask * 2   (XOR-fold partitionable threefry)
    relu_bias_dropout<<<(N * 128 + 255) / 256, 256>>>(b1, N * 128);
    // 5) p = h @ W2      (reordered: spmm(A,h)@W2 == spmm(A, h@W2) — F=64 spmm)
    gemm_k128<64, true><<<(N + 127) / 128, 256>>>(nullptr, W2, N);
    // 6) out[dst] += w * p[src]   (out pre-initialized with b2)
    spmm_f64<<<(E + 15) / 16, 256>>>(src, dst, ew, out, E);
}

// round 5
// speedup vs baseline: 1.6987x; 1.6987x over previous
#include <cuda_runtime.h>
#include <cstdint>
#include <cstddef>

// ---------------------------------------------------------------------------
// Fixed shapes: N=100000, E=1600000, F 128 -> 128 -> 64
// ---------------------------------------------------------------------------
#define MAX_N 100000
#define MAX_E 1600000
#define SCAN_CHUNK 1024
#define MAX_CHUNKS ((MAX_N + SCAN_CHUNK - 1) / SCAN_CHUNK)   // 98

// Scratch (device BSS — no allocation inside kernel_launch)
__device__ float g_buf [(size_t)MAX_N * 128];   // x @ W1
__device__ float h_buf [(size_t)MAX_N * 128];   // relu+bias+dropout(spmm1)
__device__ float p_buf [(size_t)MAX_N * 64];    // h @ W2

__device__ int   deg_buf   [MAX_N];
__device__ int   row_ptr   [MAX_N + 1];
__device__ int   cursor    [MAX_N];
__device__ int   part_buf  [MAX_CHUNKS];
__device__ int   partoff   [MAX_CHUNKS];
__device__ int   src_sorted[MAX_E];
__device__ float w_sorted  [MAX_E];

// ---------------------------------------------------------------------------
// Threefry-2x32, key = (0, 42) — bit-exact replica of jax threefry2x32 core
// ---------------------------------------------------------------------------
__device__ __forceinline__ void threefry_0_42(uint32_t x0, uint32_t x1,
                                              uint32_t& o0, uint32_t& o1)
{
    const uint32_t k0 = 0u, k1 = 42u;
    const uint32_t k2 = k0 ^ k1 ^ 0x1BD11BDAu;
    x0 += k0; x1 += k1;
#define TF_R(r) { x0 += x1; x1 = (x1 << (r)) | (x1 >> (32 - (r))); x1 ^= x0; }
    TF_R(13) TF_R(15) TF_R(26) TF_R(6)   x0 += k1; x1 += k2 + 1u;
    TF_R(17) TF_R(29) TF_R(16) TF_R(24)  x0 += k2; x1 += k0 + 2u;
    TF_R(13) TF_R(15) TF_R(26) TF_R(6)   x0 += k0; x1 += k1 + 3u;
    TF_R(17) TF_R(29) TF_R(16) TF_R(24)  x0 += k1; x1 += k2 + 4u;
    TF_R(13) TF_R(15) TF_R(26) TF_R(6)   x0 += k2; x1 += k0 + 5u;
#undef TF_R
    o0 = x0; o1 = x1;
}

// keep(i)  <=>  top bit of (o0 ^ o1) == 0    (XOR-fold, partitionable threefry)
__device__ __forceinline__ bool drop_mask(uint32_t i)
{
    uint32_t o0, o1;
    threefry_0_42(0u, i, o0, o1);
    return ((o0 ^ o1) & 0x80000000u) != 0u;   // true = drop
}

// ---------------------------------------------------------------------------
// Packed fp32x2 FMA helpers (Blackwell FFMA2)
// ---------------------------------------------------------------------------
#define FMA2(acc_, a_, b_) \
    asm("fma.rn.f32x2 %0, %1, %2, %0;" : "+l"(acc_) : "l"(a_), "l"(b_))

__device__ __forceinline__ unsigned long long dup2(float a)
{
    unsigned long long r;
    asm("mov.b64 %0, {%1, %1};" : "=l"(r) : "r"(__float_as_uint(a)));
    return r;
}

// ===========================================================================
// CSR build: deg -> scan -> scatter
// ===========================================================================
__global__ void k_zero_deg(int N)
{
    const int i = blockIdx.x * blockDim.x + threadIdx.x;
    if (i < N) deg_buf[i] = 0;
}

__global__ void k_hist(const int* __restrict__ dst, int E)
{
    const int e = blockIdx.x * blockDim.x + threadIdx.x;
    if (e < E) atomicAdd(&deg_buf[dst[e]], 1);
}

// per-chunk sums (256 threads reduce a 1024 chunk)
__global__ void k_part_sums(int N)
{
    __shared__ int sm[256];
    const int b = blockIdx.x, t = threadIdx.x;
    int s = 0;
#pragma unroll
    for (int k = 0; k < 4; k++) {
        const int i = b * SCAN_CHUNK + k * 256 + t;
        if (i < N) s += deg_buf[i];
    }
    sm[t] = s; __syncthreads();
    for (int off = 128; off > 0; off >>= 1) {
        if (t < off) sm[t] += sm[t + off];
        __syncthreads();
    }
    if (t == 0) part_buf[b] = sm[0];
}

// single-thread exclusive scan of chunk sums (<=98 elements) + row_ptr[N]=E
__global__ void k_scan_parts(int nchunks, int N, int E)
{
    if (threadIdx.x == 0 && blockIdx.x == 0) {
        int acc = 0;
        for (int c = 0; c < nchunks; c++) {
            partoff[c] = acc;
            acc += part_buf[c];
        }
        row_ptr[N] = E;   // == acc
    }
}

// per-chunk exclusive scan (1024 threads, Hillis-Steele) + global offset
__global__ void k_scan_chunks(int N)
{
    __shared__ int sm[SCAN_CHUNK];
    const int b = blockIdx.x, t = threadIdx.x;
    const int i = b * SCAN_CHUNK + t;
    const int v = (i < N) ? deg_buf[i] : 0;
    sm[t] = v; __syncthreads();
#pragma unroll
    for (int off = 1; off < SCAN_CHUNK; off <<= 1) {
        const int x = (t >= off) ? sm[t - off] : 0;
        __syncthreads();
        sm[t] += x;
        __syncthreads();
    }
    if (i < N) {
        const int ex = sm[t] - v + partoff[b];
        row_ptr[i] = ex;
        cursor[i]  = ex;
    }
}

__global__ void k_scatter(const int* __restrict__ src, const int* __restrict__ dst,
                          const float* __restrict__ ew, int E)
{
    const int e = blockIdx.x * blockDim.x + threadIdx.x;
    if (e >= E) return;
    const int pos = atomicAdd(&cursor[dst[e]], 1);
    src_sorted[pos] = src[e];
    w_sorted[pos]   = ew[e];
}

// ===========================================================================
// GEMM:  C[M, BN] = A[M, 128] @ B[128, BN]  (certified vs naive in R2/R3)
// ===========================================================================
template<int BN, bool A_IS_H>
__global__ void __launch_bounds__(256, 2)
gemm_k128(const float* __restrict__ Aarg, const float* __restrict__ B, int M)
{
    const float* __restrict__ A = A_IS_H ? h_buf : Aarg;
    float* __restrict__ C       = A_IS_H ? p_buf : g_buf;

    __shared__ __align__(16) float As[2][16 * 128];
    __shared__ __align__(16) float Bs[2][16 * BN];

    const int tid = threadIdx.x;
    const int tx  = tid & 15;
    const int ty  = tid >> 4;
    const int m0  = blockIdx.x * 128;
    const int lr  = tid >> 2;
    const int lc  = tid & 3;

    constexpr int NG = BN / 64;
    unsigned long long acc[8][2 * NG];
#pragma unroll
    for (int r = 0; r < 8; r++)
#pragma unroll
        for (int j = 0; j < 2 * NG; j++) acc[r][j] = 0ull;

    auto loadTiles = [&](int buf, int kk) {
#pragma unroll
        for (int rr = 0; rr < 2; rr++) {
            int row = m0 + lr + rr * 64;
            if (row > M - 1) row = M - 1;
            const float4 v = *(const float4*)(A + (size_t)row * 128 + kk + lc * 4);
            float* d = &As[buf][0];
            const int mi = lr + rr * 64;
            d[(lc * 4 + 0) * 128 + mi] = v.x;
            d[(lc * 4 + 1) * 128 + mi] = v.y;
            d[(lc * 4 + 2) * 128 + mi] = v.z;
            d[(lc * 4 + 3) * 128 + mi] = v.w;
        }
#pragma unroll
        for (int i = 0; i < (16 * BN) / 1024; i++) {
            const int idx = (i * 256 + tid) * 4;
            *(float4*)&Bs[buf][idx] = *(const float4*)(B + kk * BN + idx);
        }
    };

    loadTiles(0, 0);
    __syncthreads();

#pragma unroll 1
    for (int kk = 0; kk < 128; kk += 16) {
        const int cur = (kk >> 4) & 1;
        if (kk + 16 < 128) loadTiles(cur ^ 1, kk + 16);
#pragma unroll
        for (int k = 0; k < 16; k++) {
            const float4 a0 = *(const float4*)&As[cur][k * 128 + ty * 4];
            const float4 a1 = *(const float4*)&As[cur][k * 128 + ty * 4 + 64];
            unsigned long long a2[8];
            a2[0] = dup2(a0.x); a2[1] = dup2(a0.y);
            a2[2] = dup2(a0.z); a2[3] = dup2(a0.w);
            a2[4] = dup2(a1.x); a2[5] = dup2(a1.y);
            a2[6] = dup2(a1.z); a2[7] = dup2(a1.w);
#pragma unroll
            for (int g = 0; g < NG; g++) {
                const double2 b = *(const double2*)&Bs[cur][k * BN + tx * 4 + g * 64];
                const unsigned long long bl = __double_as_longlong(b.x);
                const unsigned long long bh = __double_as_longlong(b.y);
#pragma unroll
                for (int r = 0; r < 8; r++) {
                    FMA2(acc[r][2 * g + 0], a2[r], bl);
                    FMA2(acc[r][2 * g + 1], a2[r], bh);
                }
            }
        }
        __syncthreads();
    }

#pragma unroll
    for (int r = 0; r < 8; r++) {
        const int row = m0 + ty * 4 + (r >> 2) * 64 + (r & 3);
        if (row < M) {
#pragma unroll
            for (int g = 0; g < NG; g++) {
                const unsigned long long v0 = acc[r][2 * g + 0];
                const unsigned long long v1 = acc[r][2 * g + 1];
                float4 o;
                o.x = __uint_as_float((unsigned)(v0 & 0xffffffffu));
                o.y = __uint_as_float((unsigned)(v0 >> 32));
                o.z = __uint_as_float((unsigned)(v1 & 0xffffffffu));
                o.w = __uint_as_float((unsigned)(v1 >> 32));
                *(float4*)(C + (size_t)row * BN + tx * 4 + g * 64) = o;
            }
        }
    }
}

// ===========================================================================
// SpMM1 (CSR, F=128) fused with bias+relu+dropout epilogue.
// One warp per dst node; lane owns 4 features (float4); register accumulation.
// ===========================================================================
__global__ void __launch_bounds__(256)
spmm1_fused(const float* __restrict__ b1, int N)
{
    const int d    = (blockIdx.x * blockDim.x + threadIdx.x) >> 5;
    const int lane = threadIdx.x & 31;
    if (d >= N) return;

    const int beg = row_ptr[d];
    const int end = row_ptr[d + 1];

    float4 acc = make_float4(0.f, 0.f, 0.f, 0.f);
    const float* __restrict__ G = g_buf;

    int j = beg;
    for (; j + 4 <= end; j += 4) {
        const int   s0 = src_sorted[j],     s1 = src_sorted[j + 1];
        const int   s2 = src_sorted[j + 2], s3 = src_sorted[j + 3];
        const float w0 = w_sorted[j],       w1 = w_sorted[j + 1];
        const float w2 = w_sorted[j + 2],   w3 = w_sorted[j + 3];
        const float4 v0 = *(const float4*)(G + (size_t)s0 * 128 + lane * 4);
        const float4 v1 = *(const float4*)(G + (size_t)s1 * 128 + lane * 4);
        const float4 v2 = *(const float4*)(G + (size_t)s2 * 128 + lane * 4);
        const float4 v3 = *(const float4*)(G + (size_t)s3 * 128 + lane * 4);
        acc.x += w0 * v0.x + w1 * v1.x + w2 * v2.x + w3 * v3.x;
        acc.y += w0 * v0.y + w1 * v1.y + w2 * v2.y + w3 * v3.y;
        acc.z += w0 * v0.z + w1 * v1.z + w2 * v2.z + w3 * v3.z;
        acc.w += w0 * v0.w + w1 * v1.w + w2 * v2.w + w3 * v3.w;
    }
    for (; j < end; j++) {
        const int   s = src_sorted[j];
        const float w = w_sorted[j];
        const float4 v = *(const float4*)(G + (size_t)s * 128 + lane * 4);
        acc.x += w * v.x; acc.y += w * v.y; acc.z += w * v.z; acc.w += w * v.w;
    }

    // epilogue: h = relu(acc + b1) * mask * 2
    const float4 bv = *(const float4*)(b1 + lane * 4);
    const uint32_t base = (uint32_t)d * 128u + (uint32_t)lane * 4u;

    float4 o;
    float v0 = fmaxf(acc.x + bv.x, 0.f);
    float v1 = fmaxf(acc.y + bv.y, 0.f);
    float v2 = fmaxf(acc.z + bv.z, 0.f);
    float v3 = fmaxf(acc.w + bv.w, 0.f);
    o.x = drop_mask(base + 0u) ? 0.f : v0 * 2.f;
    o.y = drop_mask(base + 1u) ? 0.f : v1 * 2.f;
    o.z = drop_mask(base + 2u) ? 0.f : v2 * 2.f;
    o.w = drop_mask(base + 3u) ? 0.f : v3 * 2.f;
    *(float4*)(h_buf + (size_t)d * 128 + lane * 4) = o;
}

// ===========================================================================
// SpMM2 (CSR, F=64) fused with +b2. One warp per dst; lane owns 2 features.
// ===========================================================================
__global__ void __launch_bounds__(256)
spmm2_fused(const float* __restrict__ b2, float* __restrict__ out, int N)
{
    const int d    = (blockIdx.x * blockDim.x + threadIdx.x) >> 5;
    const int lane = threadIdx.x & 31;
    if (d >= N) return;

    const int beg = row_ptr[d];
    const int end = row_ptr[d + 1];

    float2 acc = make_float2(0.f, 0.f);
    const float* __restrict__ P = p_buf;

    int j = beg;
    for (; j + 4 <= end; j += 4) {
        const int   s0 = src_sorted[j],     s1 = src_sorted[j + 1];
        const int   s2 = src_sorted[j + 2], s3 = src_sorted[j + 3];
        const float w0 = w_sorted[j],       w1 = w_sorted[j + 1];
        const float w2 = w_sorted[j + 2],   w3 = w_sorted[j + 3];
        const float2 v0 = *(const float2*)(P + (size_t)s0 * 64 + lane * 2);
        const float2 v1 = *(const float2*)(P + (size_t)s1 * 64 + lane * 2);
        const float2 v2 = *(const float2*)(P + (size_t)s2 * 64 + lane * 2);
        const float2 v3 = *(const float2*)(P + (size_t)s3 * 64 + lane * 2);
        acc.x += w0 * v0.x + w1 * v1.x + w2 * v2.x + w3 * v3.x;
        acc.y += w0 * v0.y + w1 * v1.y + w2 * v2.y + w3 * v3.y;
    }
    for (; j < end; j++) {
        const int   s = src_sorted[j];
        const float w = w_sorted[j];
        const float2 v = *(const float2*)(P + (size_t)s * 64 + lane * 2);
        acc.x += w * v.x; acc.y += w * v.y;
    }

    const float2 bv = *(const float2*)(b2 + lane * 2);
    float2 o; o.x = acc.x + bv.x; o.y = acc.y + bv.y;
    *(float2*)(out + (size_t)d * 64 + lane * 2) = o;
}

// ---------------------------------------------------------------------------
// kernel_launch
// inputs: x, edge_weight, W1, b1, W2, b2, src, dst, n_nodes
// ---------------------------------------------------------------------------
extern "C" void kernel_launch(void* const* d_in, const int* in_sizes, int n_in,
                              void* d_out, int out_size)
{
    const float* x   = (const float*)d_in[0];
    const float* ew  = (const float*)d_in[1];
    const float* W1  = (const float*)d_in[2];
    const float* b1  = (const float*)d_in[3];
    const float* W2  = (const float*)d_in[4];
    const float* b2  = (const float*)d_in[5];
    const int*   src = (const int*)d_in[6];
    const int*   dst = (const int*)d_in[7];

    const int N = in_sizes[0] / 128;
    const int E = in_sizes[1];
    float* out = (float*)d_out;

    const int nchunks = (N + SCAN_CHUNK - 1) / SCAN_CHUNK;

    // --- CSR build (per-launch, deterministic edge sets per dst) ---
    k_zero_deg   <<<(N + 255) / 256, 256>>>(N);
    k_hist       <<<(E + 255) / 256, 256>>>(dst, E);
    k_part_sums  <<<nchunks, 256>>>(N);
    k_scan_parts <<<1, 32>>>(nchunks, N, E);
    k_scan_chunks<<<nchunks, SCAN_CHUNK>>>(N);
    k_scatter    <<<(E + 255) / 256, 256>>>(src, dst, ew, E);

    // --- pipeline ---
    // g = x @ W1
    gemm_k128<128, false><<<(N + 127) / 128, 256>>>(x, W1, N);
    // h = relu(spmm(A, g) + b1) * mask * 2     (fused epilogue)
    spmm1_fused<<<(N * 32 + 255) / 256, 256>>>(b1, N);
    // p = h @ W2
    gemm_k128<64, true><<<(N + 127) / 128, 256>>>(nullptr, W2, N);
    // out = spmm(A, p) + b2                    (fused epilogue, writes all N*64)
    spmm2_fused<<<(N * 32 + 255) / 256, 256>>>(b2, out, N);
}

// round 6
// speedup vs baseline: 1.8303x; 1.0774x over previous
#include <cuda_runtime.h>
#include <cstdint>
#include <cstddef>

// ---------------------------------------------------------------------------
// Fixed shapes: N=100000, E=1600000, F 128 -> 128 -> 64
// ---------------------------------------------------------------------------
#define MAX_N 100000
#define MAX_E 1600000
#define SCAN_CHUNK 1024
#define MAX_CHUNKS ((MAX_N + SCAN_CHUNK - 1) / SCAN_CHUNK)   // 98

// Scratch (device BSS — no allocation inside kernel_launch)
__device__ float g_buf [(size_t)MAX_N * 128];   // x @ W1
__device__ float h_buf [(size_t)MAX_N * 128];   // relu+bias+dropout(spmm1)
__device__ float p_buf [(size_t)MAX_N * 64];    // h @ W2

__device__ int   deg_buf   [MAX_N];
__device__ int   row_ptr   [MAX_N + 1];
__device__ int   cursor    [MAX_N];
__device__ int   part_buf  [MAX_CHUNKS];
__device__ int   partoff   [MAX_CHUNKS];
__device__ int   src_sorted[MAX_E];
__device__ float w_sorted  [MAX_E];

// ---------------------------------------------------------------------------
// Threefry-2x32, key = (0, 42) — bit-exact replica of jax threefry2x32 core
// ---------------------------------------------------------------------------
__device__ __forceinline__ void threefry_0_42(uint32_t x0, uint32_t x1,
                                              uint32_t& o0, uint32_t& o1)
{
    const uint32_t k0 = 0u, k1 = 42u;
    const uint32_t k2 = k0 ^ k1 ^ 0x1BD11BDAu;
    x0 += k0; x1 += k1;
#define TF_R(r) { x0 += x1; x1 = (x1 << (r)) | (x1 >> (32 - (r))); x1 ^= x0; }
    TF_R(13) TF_R(15) TF_R(26) TF_R(6)   x0 += k1; x1 += k2 + 1u;
    TF_R(17) TF_R(29) TF_R(16) TF_R(24)  x0 += k2; x1 += k0 + 2u;
    TF_R(13) TF_R(15) TF_R(26) TF_R(6)   x0 += k0; x1 += k1 + 3u;
    TF_R(17) TF_R(29) TF_R(16) TF_R(24)  x0 += k1; x1 += k2 + 4u;
    TF_R(13) TF_R(15) TF_R(26) TF_R(6)   x0 += k2; x1 += k0 + 5u;
#undef TF_R
    o0 = x0; o1 = x1;
}

// keep(i)  <=>  top bit of (o0 ^ o1) == 0    (XOR-fold, partitionable threefry)
__device__ __forceinline__ bool drop_mask(uint32_t i)
{
    uint32_t o0, o1;
    threefry_0_42(0u, i, o0, o1);
    return ((o0 ^ o1) & 0x80000000u) != 0u;   // true = drop
}

// ---------------------------------------------------------------------------
// Packed fp32x2 FMA helpers (Blackwell FFMA2)
// ---------------------------------------------------------------------------
#define FMA2(acc_, a_, b_) \
    asm("fma.rn.f32x2 %0, %1, %2, %0;" : "+l"(acc_) : "l"(a_), "l"(b_))

__device__ __forceinline__ unsigned long long dup2(float a)
{
    unsigned long long r;
    asm("mov.b64 %0, {%1, %1};" : "=l"(r) : "r"(__float_as_uint(a)));
    return r;
}

// ===========================================================================
// CSR build: deg -> scan -> scatter
// ===========================================================================
__global__ void k_zero_deg(int N)
{
    const int i = blockIdx.x * blockDim.x + threadIdx.x;
    if (i < N) deg_buf[i] = 0;
}

__global__ void k_hist(const int* __restrict__ dst, int E)
{
    const int e = blockIdx.x * blockDim.x + threadIdx.x;
    if (e < E) atomicAdd(&deg_buf[dst[e]], 1);
}

// per-chunk sums (256 threads reduce a 1024 chunk)
__global__ void k_part_sums(int N)
{
    __shared__ int sm[256];
    const int b = blockIdx.x, t = threadIdx.x;
    int s = 0;
#pragma unroll
    for (int k = 0; k < 4; k++) {
        const int i = b * SCAN_CHUNK + k * 256 + t;
        if (i < N) s += deg_buf[i];
    }
    sm[t] = s; __syncthreads();
    for (int off = 128; off > 0; off >>= 1) {
        if (t < off) sm[t] += sm[t + off];
        __syncthreads();
    }
    if (t == 0) part_buf[b] = sm[0];
}

// parallel single-block exclusive scan of chunk sums (<=128) + row_ptr[N]=E
__global__ void k_scan_parts(int nchunks, int N, int E)
{
    __shared__ int sm[128];
    const int t = threadIdx.x;
    const int v = (t < nchunks) ? part_buf[t] : 0;
    sm[t] = v; __syncthreads();
#pragma unroll
    for (int off = 1; off < 128; off <<= 1) {
        const int x = (t >= off) ? sm[t - off] : 0;
        __syncthreads();
        sm[t] += x;
        __syncthreads();
    }
    if (t < nchunks) partoff[t] = sm[t] - v;   // exclusive
    if (t == 0) row_ptr[N] = E;
}

// per-chunk exclusive scan (1024 threads, Hillis-Steele) + global offset
__global__ void k_scan_chunks(int N)
{
    __shared__ int sm[SCAN_CHUNK];
    const int b = blockIdx.x, t = threadIdx.x;
    const int i = b * SCAN_CHUNK + t;
    const int v = (i < N) ? deg_buf[i] : 0;
    sm[t] = v; __syncthreads();
#pragma unroll
    for (int off = 1; off < SCAN_CHUNK; off <<= 1) {
        const int x = (t >= off) ? sm[t - off] : 0;
        __syncthreads();
        sm[t] += x;
        __syncthreads();
    }
    if (i < N) {
        const int ex = sm[t] - v + partoff[b];
        row_ptr[i] = ex;
        cursor[i]  = ex;
    }
}

__global__ void k_scatter(const int* __restrict__ src, const int* __restrict__ dst,
                          const float* __restrict__ ew, int E)
{
    const int e = blockIdx.x * blockDim.x + threadIdx.x;
    if (e >= E) return;
    const int pos = atomicAdd(&cursor[dst[e]], 1);
    src_sorted[pos] = src[e];
    w_sorted[pos]   = ew[e];
}

// ===========================================================================
// GEMM:  C[M, BN] = A[M, 128] @ B[128, BN]  (certified vs naive in R2/R3)
// ===========================================================================
template<int BN, bool A_IS_H>
__global__ void __launch_bounds__(256, 2)
gemm_k128(const float* __restrict__ Aarg, const float* __restrict__ B, int M)
{
    const float* __restrict__ A = A_IS_H ? h_buf : Aarg;
    float* __restrict__ C       = A_IS_H ? p_buf : g_buf;

    __shared__ __align__(16) float As[2][16 * 128];
    __shared__ __align__(16) float Bs[2][16 * BN];

    const int tid = threadIdx.x;
    const int tx  = tid & 15;
    const int ty  = tid >> 4;
    const int m0  = blockIdx.x * 128;
    const int lr  = tid >> 2;
    const int lc  = tid & 3;

    constexpr int NG = BN / 64;
    unsigned long long acc[8][2 * NG];
#pragma unroll
    for (int r = 0; r < 8; r++)
#pragma unroll
        for (int j = 0; j < 2 * NG; j++) acc[r][j] = 0ull;

    auto loadTiles = [&](int buf, int kk) {
#pragma unroll
        for (int rr = 0; rr < 2; rr++) {
            int row = m0 + lr + rr * 64;
            if (row > M - 1) row = M - 1;
            const float4 v = *(const float4*)(A + (size_t)row * 128 + kk + lc * 4);
            float* d = &As[buf][0];
            const int mi = lr + rr * 64;
            d[(lc * 4 + 0) * 128 + mi] = v.x;
            d[(lc * 4 + 1) * 128 + mi] = v.y;
            d[(lc * 4 + 2) * 128 + mi] = v.z;
            d[(lc * 4 + 3) * 128 + mi] = v.w;
        }
#pragma unroll
        for (int i = 0; i < (16 * BN) / 1024; i++) {
            const int idx = (i * 256 + tid) * 4;
            *(float4*)&Bs[buf][idx] = *(const float4*)(B + kk * BN + idx);
        }
    };

    loadTiles(0, 0);
    __syncthreads();

#pragma unroll 1
    for (int kk = 0; kk < 128; kk += 16) {
        const int cur = (kk >> 4) & 1;
        if (kk + 16 < 128) loadTiles(cur ^ 1, kk + 16);
#pragma unroll
        for (int k = 0; k < 16; k++) {
            const float4 a0 = *(const float4*)&As[cur][k * 128 + ty * 4];
            const float4 a1 = *(const float4*)&As[cur][k * 128 + ty * 4 + 64];
            unsigned long long a2[8];
            a2[0] = dup2(a0.x); a2[1] = dup2(a0.y);
            a2[2] = dup2(a0.z); a2[3] = dup2(a0.w);
            a2[4] = dup2(a1.x); a2[5] = dup2(a1.y);
            a2[6] = dup2(a1.z); a2[7] = dup2(a1.w);
#pragma unroll
            for (int g = 0; g < NG; g++) {
                const double2 b = *(const double2*)&Bs[cur][k * BN + tx * 4 + g * 64];
                const unsigned long long bl = __double_as_longlong(b.x);
                const unsigned long long bh = __double_as_longlong(b.y);
#pragma unroll
                for (int r = 0; r < 8; r++) {
                    FMA2(acc[r][2 * g + 0], a2[r], bl);
                    FMA2(acc[r][2 * g + 1], a2[r], bh);
                }
            }
        }
        __syncthreads();
    }

#pragma unroll
    for (int r = 0; r < 8; r++) {
        const int row = m0 + ty * 4 + (r >> 2) * 64 + (r & 3);
        if (row < M) {
#pragma unroll
            for (int g = 0; g < NG; g++) {
                const unsigned long long v0 = acc[r][2 * g + 0];
                const unsigned long long v1 = acc[r][2 * g + 1];
                float4 o;
                o.x = __uint_as_float((unsigned)(v0 & 0xffffffffu));
                o.y = __uint_as_float((unsigned)(v0 >> 32));
                o.z = __uint_as_float((unsigned)(v1 & 0xffffffffu));
                o.w = __uint_as_float((unsigned)(v1 >> 32));
                *(float4*)(C + (size_t)row * BN + tx * 4 + g * 64) = o;
            }
        }
    }
}

// ===========================================================================
// SpMM1 (CSR, F=128) fused with bias+relu+dropout epilogue.
// One warp per dst node; lane owns 4 features (float4); register accumulation.
// ===========================================================================
__global__ void __launch_bounds__(256)
spmm1_fused(const float* __restrict__ b1, int N)
{
    const int d    = (blockIdx.x * blockDim.x + threadIdx.x) >> 5;
    const int lane = threadIdx.x & 31;
    if (d >= N) return;

    const int beg = row_ptr[d];
    const int end = row_ptr[d + 1];

    float4 acc = make_float4(0.f, 0.f, 0.f, 0.f);
    const float* __restrict__ G = g_buf;

    int j = beg;
    for (; j + 4 <= end; j += 4) {
        const int   s0 = src_sorted[j],     s1 = src_sorted[j + 1];
        const int   s2 = src_sorted[j + 2], s3 = src_sorted[j + 3];
        const float w0 = w_sorted[j],       w1 = w_sorted[j + 1];
        const float w2 = w_sorted[j + 2],   w3 = w_sorted[j + 3];
        const float4 v0 = *(const float4*)(G + (size_t)s0 * 128 + lane * 4);
        const float4 v1 = *(const float4*)(G + (size_t)s1 * 128 + lane * 4);
        const float4 v2 = *(const float4*)(G + (size_t)s2 * 128 + lane * 4);
        const float4 v3 = *(const float4*)(G + (size_t)s3 * 128 + lane * 4);
        acc.x += w0 * v0.x + w1 * v1.x + w2 * v2.x + w3 * v3.x;
        acc.y += w0 * v0.y + w1 * v1.y + w2 * v2.y + w3 * v3.y;
        acc.z += w0 * v0.z + w1 * v1.z + w2 * v2.z + w3 * v3.z;
        acc.w += w0 * v0.w + w1 * v1.w + w2 * v2.w + w3 * v3.w;
    }
    for (; j < end; j++) {
        const int   s = src_sorted[j];
        const float w = w_sorted[j];
        const float4 v = *(const float4*)(G + (size_t)s * 128 + lane * 4);
        acc.x += w * v.x; acc.y += w * v.y; acc.z += w * v.z; acc.w += w * v.w;
    }

    // epilogue: h = relu(acc + b1) * mask * 2
    const float4 bv = *(const float4*)(b1 + lane * 4);
    const uint32_t base = (uint32_t)d * 128u + (uint32_t)lane * 4u;

    float4 o;
    float v0 = fmaxf(acc.x + bv.x, 0.f);
    float v1 = fmaxf(acc.y + bv.y, 0.f);
    float v2 = fmaxf(acc.z + bv.z, 0.f);
    float v3 = fmaxf(acc.w + bv.w, 0.f);
    o.x = drop_mask(base + 0u) ? 0.f : v0 * 2.f;
    o.y = drop_mask(base + 1u) ? 0.f : v1 * 2.f;
    o.z = drop_mask(base + 2u) ? 0.f : v2 * 2.f;
    o.w = drop_mask(base + 3u) ? 0.f : v3 * 2.f;
    *(float4*)(h_buf + (size_t)d * 128 + lane * 4) = o;
}

// ===========================================================================
// SpMM2 (CSR, F=64) fused with +b2. One warp per dst; lane owns 2 features.
// 8-edge unroll for deeper MLP.
// ===========================================================================
__global__ void __launch_bounds__(256)
spmm2_fused(const float* __restrict__ b2, float* __restrict__ out, int N)
{
    const int d    = (blockIdx.x * blockDim.x + threadIdx.x) >> 5;
    const int lane = threadIdx.x & 31;
    if (d >= N) return;

    const int beg = row_ptr[d];
    const int end = row_ptr[d + 1];

    float2 acc = make_float2(0.f, 0.f);
    const float* __restrict__ P = p_buf;

    int j = beg;
    for (; j + 8 <= end; j += 8) {
        int   s[8]; float w[8]; float2 v[8];
#pragma unroll
        for (int q = 0; q < 8; q++) { s[q] = src_sorted[j + q]; w[q] = w_sorted[j + q]; }
#pragma unroll
        for (int q = 0; q < 8; q++) v[q] = *(const float2*)(P + (size_t)s[q] * 64 + lane * 2);
#pragma unroll
        for (int q = 0; q < 8; q++) { acc.x += w[q] * v[q].x; acc.y += w[q] * v[q].y; }
    }
    for (; j < end; j++) {
        const int   s = src_sorted[j];
        const float w = w_sorted[j];
        const float2 v = *(const float2*)(P + (size_t)s * 64 + lane * 2);
        acc.x += w * v.x; acc.y += w * v.y;
    }

    const float2 bv = *(const float2*)(b2 + lane * 2);
    float2 o; o.x = acc.x + bv.x; o.y = acc.y + bv.y;
    *(float2*)(out + (size_t)d * 64 + lane * 2) = o;
}

// ---------------------------------------------------------------------------
// kernel_launch
// inputs: x, edge_weight, W1, b1, W2, b2, src, dst, n_nodes
//
// CSR build runs on a secondary stream, overlapped with gemm1 (independent).
// Fork-join via events — the standard multi-stream graph-capture pattern.
// Stream/events are created lazily on the first (non-captured) call.
// ---------------------------------------------------------------------------
extern "C" void kernel_launch(void* const* d_in, const int* in_sizes, int n_in,
                              void* d_out, int out_size)
{
    const float* x   = (const float*)d_in[0];
    const float* ew  = (const float*)d_in[1];
    const float* W1  = (const float*)d_in[2];
    const float* b1  = (const float*)d_in[3];
    const float* W2  = (const float*)d_in[4];
    const float* b2  = (const float*)d_in[5];
    const int*   src = (const int*)d_in[6];
    const int*   dst = (const int*)d_in[7];

    const int N = in_sizes[0] / 128;
    const int E = in_sizes[1];
    float* out = (float*)d_out;

    const int nchunks = (N + SCAN_CHUNK - 1) / SCAN_CHUNK;

    static cudaStream_t s2 = nullptr;
    static cudaEvent_t  ev_fork = nullptr, ev_join = nullptr;
    static bool tried = false;
    if (!tried) {
        tried = true;
        if (cudaStreamCreateWithFlags(&s2, cudaStreamNonBlocking) != cudaSuccess) s2 = nullptr;
        if (s2) {
            cudaEventCreateWithFlags(&ev_fork, cudaEventDisableTiming);
            cudaEventCreateWithFlags(&ev_join, cudaEventDisableTiming);
        }
    }

    cudaStream_t cs = s2 ? s2 : (cudaStream_t)0;   // CSR stream (fallback: main)

    if (s2) {
        cudaEventRecord(ev_fork, 0);
        cudaStreamWaitEvent(s2, ev_fork, 0);
    }

    // --- CSR build (independent of gemm1) on cs ---
    k_zero_deg   <<<(N + 255) / 256, 256, 0, cs>>>(N);
    k_hist       <<<(E + 255) / 256, 256, 0, cs>>>(dst, E);
    k_part_sums  <<<nchunks, 256, 0, cs>>>(N);
    k_scan_parts <<<1, 128, 0, cs>>>(nchunks, N, E);
    k_scan_chunks<<<nchunks, SCAN_CHUNK, 0, cs>>>(N);
    k_scatter    <<<(E + 255) / 256, 256, 0, cs>>>(src, dst, ew, E);

    if (s2) cudaEventRecord(ev_join, s2);

    // --- gemm1 on main stream, overlapped with CSR build ---
    gemm_k128<128, false><<<(N + 127) / 128, 256>>>(x, W1, N);

    if (s2) cudaStreamWaitEvent((cudaStream_t)0, ev_join, 0);

    // h = relu(spmm(A, g) + b1) * mask * 2     (fused epilogue)
    spmm1_fused<<<(N * 32 + 255) / 256, 256>>>(b1, N);
    // p = h @ W2
    gemm_k128<64, true><<<(N + 127) / 128, 256>>>(nullptr, W2, N);
    // out = spmm(A, p) + b2                    (fused epilogue, writes all N*64)
    spmm2_fused<<<(N * 32 + 255) / 256, 256>>>(b2, out, N);
}